// round 13
// baseline (speedup 1.0000x reference)
#include <cuda_runtime.h>

// GRUAdder: B = 1048576, T=4, I=2, H=16.
// L=4 lanes per row (lane q owns h[4q..4q+3], gates {4q..4q+3} of r/z/n),
// D=2 rows per thread. k-parity f32x2 accumulators; shfl64 of owner's packed
// h feeds ffma2 directly. Weights streamed from shared via LDS.128 with a
// wavefront-exact [kp][slot-pair][q] layout (4 lanes read 4 consecutive 16B
// chunks -> 1 wavefront/instruction, broadcast across groups).
// Sigmoid via tanh.approx (0.5 pre-folded into staged weights); n-gate tanh
// via ex2/rcp with -2*log2(e) pre-folded.

#define TT 4
#define II 2
#define HH 16
#define LROWS 4   // iterations; rows per warp = 16 * LROWS = 64

#define SRZ 0.5f
#define SN  (-2.8853900817779268f)   // -2*log2(e)

typedef unsigned long long ull;

__device__ __forceinline__ ull ffma2(ull a, ull b, ull c) {
    ull d;
    asm("fma.rn.f32x2 %0, %1, %2, %3;" : "=l"(d) : "l"(a), "l"(b), "l"(c));
    return d;
}
__device__ __forceinline__ ull pk2(float lo, float hi) {
    ull r;
    asm("mov.b64 %0, {%1, %2};" : "=l"(r) : "f"(lo), "f"(hi));
    return r;
}
__device__ __forceinline__ void upk2(float& lo, float& hi, ull v) {
    asm("mov.b64 {%0, %1}, %2;" : "=f"(lo), "=f"(hi) : "l"(v));
}
__device__ __forceinline__ float hadd2(ull v) {
    float lo, hi;
    upk2(lo, hi, v);
    return lo + hi;
}
__device__ __forceinline__ float tanhapx(float x) {
    float r;
    asm("tanh.approx.f32 %0, %1;" : "=f"(r) : "f"(x));
    return r;
}
// argument already scaled by -2*log2(e): returns tanh(y) where a = SN*y
__device__ __forceinline__ float ftanh_prescaled(float a) {
    float e, r;
    asm("ex2.approx.f32 %0, %1;" : "=f"(e) : "f"(a));
    asm("rcp.approx.f32 %0, %1;" : "=f"(r) : "f"(1.0f + e));
    return fmaf(2.0f, r, -1.0f);
}

__global__ void __launch_bounds__(128) gru_adder_kernel(
    const float* __restrict__ x,        // [B, 4, 2]
    const float* __restrict__ w_ih,     // [48, 2]
    const float* __restrict__ w_hh,     // [48, 16]
    const float* __restrict__ b_ih,     // [48]
    const float* __restrict__ b_hh,     // [48]
    const float* __restrict__ w_sum,    // [1, 16]
    const float* __restrict__ b_sum,    // [1]
    const float* __restrict__ w_carry,  // [1, 16]
    const float* __restrict__ b_carry,  // [1]
    float* __restrict__ hid,            // [B, 4, 16]
    float* __restrict__ sumo,           // [B, 4]
    float* __restrict__ carryo,         // [B]
    float* __restrict__ olog,           // [B, 5]
    long long B)
{
    // Slot s = cat*4 + m (cat: 0=r,1=z,2=n; m=0..3); gate j = cat*16 + 4q + m.
    // Slot-pair sp covers s = 2sp, 2sp+1 (both in one category).
    // sh_wp[kp][sp][q].x = (sc*w_hh[j(2sp)][2kp],   sc*w_hh[j(2sp)][2kp+1])
    // sh_wp[kp][sp][q].y = (sc*w_hh[j(2sp+1)][2kp], sc*w_hh[j(2sp+1)][2kp+1])
    // sc = 0.5 (r,z), SN (n).  One LDS.128 per (kp,sp) -> 1 wavefront.
    __shared__ __align__(16) ulonglong2 sh_wp[8][6][4];
    __shared__ __align__(16) ulonglong2 sh_wx[6][4];   // (sc*wih0, sc*wih1) pairs
    __shared__ __align__(16) ulonglong2 sh_b2[6][4];   // bias seeds (packed,0)
    __shared__ __align__(16) ulonglong2 sh_gb[2][4];   // n-gate input bias pairs
    __shared__ __align__(16) float sh_wsum[16], sh_wcar[16];
    __shared__ float sh_bs, sh_bc;

    const int tidb = threadIdx.x;
    for (int idx = tidb; idx < 192; idx += 128) {
        int kp = idx / 24, rem = idx % 24, sp = rem / 4, qq = rem % 4;
        int s0 = 2 * sp, s1 = 2 * sp + 1;
        int cat = s0 >> 2;
        int j0 = cat * 16 + 4 * qq + (s0 & 3);
        int j1 = cat * 16 + 4 * qq + (s1 & 3);
        float sc = (cat < 2) ? SRZ : SN;
        ulonglong2 v;
        v.x = pk2(sc * w_hh[j0 * HH + 2 * kp], sc * w_hh[j0 * HH + 2 * kp + 1]);
        v.y = pk2(sc * w_hh[j1 * HH + 2 * kp], sc * w_hh[j1 * HH + 2 * kp + 1]);
        sh_wp[kp][sp][qq] = v;
    }
    if (tidb < 24) {
        int sp = tidb / 4, qq = tidb % 4;
        int s0 = 2 * sp, s1 = 2 * sp + 1;
        int cat = s0 >> 2;
        int j0 = cat * 16 + 4 * qq + (s0 & 3);
        int j1 = cat * 16 + 4 * qq + (s1 & 3);
        float sc = (cat < 2) ? SRZ : SN;
        ulonglong2 w;
        w.x = pk2(sc * w_ih[j0 * II + 0], sc * w_ih[j0 * II + 1]);
        w.y = pk2(sc * w_ih[j1 * II + 0], sc * w_ih[j1 * II + 1]);
        sh_wx[sp][qq] = w;
        ulonglong2 b;
        if (cat < 2) {
            b.x = pk2(SRZ * (b_ih[j0] + b_hh[j0]), 0.0f);
            b.y = pk2(SRZ * (b_ih[j1] + b_hh[j1]), 0.0f);
        } else {
            b.x = pk2(SN * b_hh[j0], 0.0f);
            b.y = pk2(SN * b_hh[j1], 0.0f);
        }
        sh_b2[sp][qq] = b;
        if (sp >= 4) {   // n-gate input biases, pairs (m0,m1) = (2*(sp-4), +1)
            ulonglong2 g;
            g.x = pk2(SN * b_ih[j0], 0.0f);
            g.y = pk2(SN * b_ih[j1], 0.0f);
            sh_gb[sp - 4][qq] = g;
        }
    }
    if (tidb < 16) {
        sh_wsum[tidb] = w_sum[tidb];
        sh_wcar[tidb] = w_carry[tidb];
        if (tidb == 0) { sh_bs = b_sum[0]; sh_bc = b_carry[0]; }
    }
    __syncthreads();

    const int lane    = tidb & 31;
    const int q       = lane & 3;
    const int grpbase = lane & 28;
    const int g       = lane >> 2;

    const ulonglong2* wq  = &sh_wp[0][0][q];   // stride 4 entries per sp, 24 per kp
    const ulonglong2* wxq = &sh_wx[0][q];
    const ulonglong2* b2q = &sh_b2[0][q];
    const ulonglong2* gbq = &sh_gb[0][q];
    const float ws0 = sh_wsum[4*q+0], ws1 = sh_wsum[4*q+1];
    const float ws2 = sh_wsum[4*q+2], ws3 = sh_wsum[4*q+3];
    const float wc0 = sh_wcar[4*q+0], wc1 = sh_wcar[4*q+1];
    const float wc2 = sh_wcar[4*q+2], wc3 = sh_wcar[4*q+3];
    const float bs = sh_bs, bc = sh_bc;

    const int  warp_global = blockIdx.x * (blockDim.x >> 5) + (tidb >> 5);
    const long long rowbase0 = (long long)warp_global * (16 * LROWS);
    if (rowbase0 >= B) return;

    #pragma unroll 1
    for (int it = 0; it < LROWS; it++) {
        const long long rowA = rowbase0 + it * 16 + g;
        const long long rowB = rowA + 8;
        const long long rAs = (rowA < B) ? rowA : 0;
        const long long rBs = (rowB < B) ? rowB : 0;
        const bool okA = (rowA < B), okB = (rowB < B);

        ull hL[2] = {0, 0};   // (h[4q],   h[4q+1]) per row
        ull hH[2] = {0, 0};   // (h[4q+2], h[4q+3]) per row

        #pragma unroll 1
        for (int t = 0; t < TT; t++) {
            const float2 xA = *reinterpret_cast<const float2*>(x + rAs * (TT*II) + t*II);
            const float2 xB = *reinterpret_cast<const float2*>(x + rBs * (TT*II) + t*II);
            const ull xpA = pk2(xA.x, xA.y);
            const ull xpB = pk2(xB.x, xB.y);

            ull acc[2][12];   // k-parity packed, slot-indexed
            ull gin[2][4];    // n-gate input part (prescaled by SN)

            #pragma unroll
            for (int sp = 0; sp < 4; sp++) {      // r,z gates: x + bias
                const ulonglong2 w = wxq[sp * 4];
                const ulonglong2 b = b2q[sp * 4];
                acc[0][2*sp+0] = ffma2(w.x, xpA, b.x);
                acc[0][2*sp+1] = ffma2(w.y, xpA, b.y);
                acc[1][2*sp+0] = ffma2(w.x, xpB, b.x);
                acc[1][2*sp+1] = ffma2(w.y, xpB, b.y);
            }
            #pragma unroll
            for (int sp = 4; sp < 6; sp++) {      // n gates: split rec/input
                const ulonglong2 b = b2q[sp * 4];
                acc[0][2*sp+0] = b.x;
                acc[0][2*sp+1] = b.y;
                acc[1][2*sp+0] = b.x;
                acc[1][2*sp+1] = b.y;
                const ulonglong2 w  = wxq[sp * 4];
                const ulonglong2 gb = gbq[(sp - 4) * 4];
                gin[0][2*(sp-4)+0] = ffma2(w.x, xpA, gb.x);
                gin[0][2*(sp-4)+1] = ffma2(w.y, xpA, gb.y);
                gin[1][2*(sp-4)+0] = ffma2(w.x, xpB, gb.x);
                gin[1][2*(sp-4)+1] = ffma2(w.y, xpB, gb.y);
            }

            // matvec over 8 k-pairs: 6 LDS.128 (1 wavefront each) + 2 shfl64
            // + 24 ffma2 per k-pair.
            #pragma unroll
            for (int kp = 0; kp < 8; kp++) {
                const int src = grpbase | (kp >> 1);
                const ull hbA = __shfl_sync(0xffffffffu, (kp & 1) ? hH[0] : hL[0], src);
                const ull hbB = __shfl_sync(0xffffffffu, (kp & 1) ? hH[1] : hL[1], src);
                const ulonglong2* wp = wq + kp * 24;
                #pragma unroll
                for (int sp = 0; sp < 6; sp++) {
                    const ulonglong2 w = wp[sp * 4];
                    acc[0][2*sp+0] = ffma2(w.x, hbA, acc[0][2*sp+0]);
                    acc[0][2*sp+1] = ffma2(w.y, hbA, acc[0][2*sp+1]);
                    acc[1][2*sp+0] = ffma2(w.x, hbB, acc[1][2*sp+0]);
                    acc[1][2*sp+1] = ffma2(w.y, hbB, acc[1][2*sp+1]);
                }
            }

            // epilogue + heads per row
            #pragma unroll
            for (int i = 0; i < 2; i++) {
                float hp0, hp1, hp2, hp3;
                upk2(hp0, hp1, hL[i]);
                upk2(hp2, hp3, hH[i]);
                const float r0 = fmaf(tanhapx(hadd2(acc[i][0])), 0.5f, 0.5f);
                const float r1 = fmaf(tanhapx(hadd2(acc[i][1])), 0.5f, 0.5f);
                const float r2 = fmaf(tanhapx(hadd2(acc[i][2])), 0.5f, 0.5f);
                const float r3 = fmaf(tanhapx(hadd2(acc[i][3])), 0.5f, 0.5f);
                const float z0 = fmaf(tanhapx(hadd2(acc[i][4])), 0.5f, 0.5f);
                const float z1 = fmaf(tanhapx(hadd2(acc[i][5])), 0.5f, 0.5f);
                const float z2 = fmaf(tanhapx(hadd2(acc[i][6])), 0.5f, 0.5f);
                const float z3 = fmaf(tanhapx(hadd2(acc[i][7])), 0.5f, 0.5f);
                const float n0 = ftanh_prescaled(fmaf(r0, hadd2(acc[i][8]),  hadd2(gin[i][0])));
                const float n1 = ftanh_prescaled(fmaf(r1, hadd2(acc[i][9]),  hadd2(gin[i][1])));
                const float n2 = ftanh_prescaled(fmaf(r2, hadd2(acc[i][10]), hadd2(gin[i][2])));
                const float n3 = ftanh_prescaled(fmaf(r3, hadd2(acc[i][11]), hadd2(gin[i][3])));
                const float h0 = fmaf(z0, hp0 - n0, n0);   // (1-z)*n + z*h
                const float h1 = fmaf(z1, hp1 - n1, n1);
                const float h2 = fmaf(z2, hp2 - n2, n2);
                const float h3 = fmaf(z3, hp3 - n3, n3);
                hL[i] = pk2(h0, h1);
                hH[i] = pk2(h2, h3);

                float sp = fmaf(h3, ws3, fmaf(h2, ws2, fmaf(h1, ws1, h0 * ws0)));
                sp += __shfl_xor_sync(0xffffffffu, sp, 1);
                sp += __shfl_xor_sync(0xffffffffu, sp, 2);

                const long long row = i ? rowB : rowA;
                const bool ok = i ? okB : okA;
                if (ok) {
                    if (hid)
                        *reinterpret_cast<float4*>(hid + row * (TT*HH) + t*HH + 4*q) =
                            make_float4(h0, h1, h2, h3);
                    if (q == 0) {
                        if (sumo) sumo[row * TT + t] = bs + sp;
                    } else if (q == 1) {
                        if (olog) olog[row * (TT+1) + t] = bs + sp;
                    }
                }
            }
        }

        // carry head
        #pragma unroll
        for (int i = 0; i < 2; i++) {
            float h0, h1, h2, h3;
            upk2(h0, h1, hL[i]);
            upk2(h2, h3, hH[i]);
            float cp = fmaf(h3, wc3, fmaf(h2, wc2, fmaf(h1, wc1, h0 * wc0)));
            cp += __shfl_xor_sync(0xffffffffu, cp, 1);
            cp += __shfl_xor_sync(0xffffffffu, cp, 2);
            const long long row = i ? rowB : rowA;
            const bool ok = i ? okB : okA;
            if (ok) {
                if (q == 2) {
                    if (carryo) carryo[row] = bc + cp;
                } else if (q == 3) {
                    if (olog) olog[row * (TT+1) + TT] = bc + cp;
                }
            }
        }
    }
}

extern "C" void kernel_launch(void* const* d_in, const int* in_sizes, int n_in,
                              void* d_out, int out_size) {
    const float* x       = (const float*)d_in[0];
    const float* w_ih    = (const float*)d_in[1];
    const float* w_hh    = (const float*)d_in[2];
    const float* b_ih    = (const float*)d_in[3];
    const float* b_hh    = (const float*)d_in[4];
    const float* w_sum   = (const float*)d_in[5];
    const float* b_sum   = (const float*)d_in[6];
    const float* w_carry = (const float*)d_in[7];
    const float* b_carry = (const float*)d_in[8];

    long long B = (long long)in_sizes[0] / (TT * II);
    float* out = (float*)d_out;
    long long os = (long long)out_size;

    // Output layout: concatenation of flattened (hidden_table, sum_logits,
    // carry_logit, output_logits) = 74 floats per row; fall back otherwise.
    float *hid = nullptr, *sum = nullptr, *car = nullptr, *olog = nullptr;
    if (os >= B * 74) {
        hid = out; sum = out + B * 64; car = out + B * 68; olog = out + B * 69;
    } else if (os >= B * 64) {
        hid = out;
    } else if (os >= B * 5) {
        olog = out;
    } else if (os >= B * 4) {
        sum = out;
    } else {
        car = out;
    }

    const int threads = 128;                        // 4 warps per CTA
    const long long rows_per_warp = 16 * LROWS;     // 64
    long long warps = (B + rows_per_warp - 1) / rows_per_warp;
    long long ctas  = (warps + 3) / 4;
    gru_adder_kernel<<<(int)ctas, threads>>>(x, w_ih, w_hh, b_ih, b_hh,
                                             w_sum, b_sum, w_carry, b_carry,
                                             hid, sum, car, olog, B);
}

// round 14
// speedup vs baseline: 1.2388x; 1.2388x over previous
#include <cuda_runtime.h>

// GRUAdder: B = 1048576, T=4, I=2, H=16.
// L=4 lanes per row (lane q owns h[4q..4q+3], gates {4q..4q+3} of r/z/n),
// D=3 rows per thread. Gate-pair packed f32x2 accumulators (8 ull per row).
// h exchanged through a per-warp SMEM buffer holding h DUPLICATED (h_j,h_j):
// matvec reads one LDS.128 per 2 k per row and feeds ffma2 directly — no
// shuffles, no packing movs in the inner loop. 144B row stride -> phase
// conflict-free. Weights streamed via wavefront-exact LDS.128.
// Sigmoid via tanh.approx (0.5 pre-folded); n-tanh via ex2/rcp (SN pre-folded).

#define TT 4
#define II 2
#define HH 16
#define LROWS 2         // iterations; rows per warp = 24 * LROWS = 48
#define RPW 24          // rows in flight per warp (8 groups x 3)
#define RBS 9           // rowbuf slot stride in ulonglong2 (144 B)

#define SRZ 0.5f
#define SN  (-2.8853900817779268f)   // -2*log2(e)

typedef unsigned long long ull;

__device__ __forceinline__ ull ffma2(ull a, ull b, ull c) {
    ull d;
    asm("fma.rn.f32x2 %0, %1, %2, %3;" : "=l"(d) : "l"(a), "l"(b), "l"(c));
    return d;
}
__device__ __forceinline__ ull pk2(float lo, float hi) {
    ull r;
    asm("mov.b64 %0, {%1, %2};" : "=l"(r) : "f"(lo), "f"(hi));
    return r;
}
__device__ __forceinline__ void upk2(float& lo, float& hi, ull v) {
    asm("mov.b64 {%0, %1}, %2;" : "=f"(lo), "=f"(hi) : "l"(v));
}
__device__ __forceinline__ float tanhapx(float x) {
    float r;
    asm("tanh.approx.f32 %0, %1;" : "=f"(r) : "f"(x));
    return r;
}
// argument already scaled by -2*log2(e): returns tanh(y) where a = SN*y
__device__ __forceinline__ float ftanh_prescaled(float a) {
    float e, r;
    asm("ex2.approx.f32 %0, %1;" : "=f"(e) : "f"(a));
    asm("rcp.approx.f32 %0, %1;" : "=f"(r) : "f"(1.0f + e));
    return fmaf(2.0f, r, -1.0f);
}

__global__ void __launch_bounds__(128) gru_adder_kernel(
    const float* __restrict__ x,        // [B, 4, 2]
    const float* __restrict__ w_ih,     // [48, 2]
    const float* __restrict__ w_hh,     // [48, 16]
    const float* __restrict__ b_ih,     // [48]
    const float* __restrict__ b_hh,     // [48]
    const float* __restrict__ w_sum,    // [1, 16]
    const float* __restrict__ b_sum,    // [1]
    const float* __restrict__ w_carry,  // [1, 16]
    const float* __restrict__ b_carry,  // [1]
    float* __restrict__ hid,            // [B, 4, 16]
    float* __restrict__ sumo,           // [B, 4]
    float* __restrict__ carryo,         // [B]
    float* __restrict__ olog,           // [B, 5]
    long long B)
{
    // Weights, gate-pair packed: sh_whh[k*12 + cat*4 + q] =
    //   { pk2(sc*w[j][k], sc*w[j+1][k]), pk2(sc*w[j+2][k], sc*w[j+3][k]) }
    //   with j = cat*16 + 4q; sc = 0.5 (r,z), SN (n).
    __shared__ __align__(16) ulonglong2 sh_whh[16 * 12];
    __shared__ __align__(16) ulonglong2 sh_wx[2 * 12];   // per input col
    __shared__ __align__(16) ulonglong2 sh_bias[12];     // pair bias seeds
    __shared__ __align__(16) ulonglong2 sh_gbias[4];     // n input-bias pairs
    __shared__ __align__(16) float sh_wsum[16], sh_wcar[16];
    __shared__ float sh_bs, sh_bc;
    // Per-warp h buffer: RPW slots x 144B; slot holds 16 duplicated h (128B).
    __shared__ __align__(16) ulonglong2 sh_rb[4 * RPW * RBS];

    const int tidb = threadIdx.x;
    for (int idx = tidb; idx < 192; idx += 128) {
        int k = idx / 12, rem = idx % 12, cat = rem / 4, qq = rem % 4;
        int j = cat * 16 + 4 * qq;
        float sc = (cat < 2) ? SRZ : SN;
        ulonglong2 v;
        v.x = pk2(sc * w_hh[(j + 0) * HH + k], sc * w_hh[(j + 1) * HH + k]);
        v.y = pk2(sc * w_hh[(j + 2) * HH + k], sc * w_hh[(j + 3) * HH + k]);
        sh_whh[idx] = v;
    }
    if (tidb < 24) {
        int col = tidb / 12, rem = tidb % 12, cat = rem / 4, qq = rem % 4;
        int j = cat * 16 + 4 * qq;
        float sc = (cat < 2) ? SRZ : SN;
        ulonglong2 v;
        v.x = pk2(sc * w_ih[(j + 0) * II + col], sc * w_ih[(j + 1) * II + col]);
        v.y = pk2(sc * w_ih[(j + 2) * II + col], sc * w_ih[(j + 3) * II + col]);
        sh_wx[tidb] = v;
    }
    if (tidb < 12) {
        int cat = tidb / 4, qq = tidb % 4;
        int j = cat * 16 + 4 * qq;
        ulonglong2 v;
        if (cat < 2) {
            v.x = pk2(SRZ * (b_ih[j+0] + b_hh[j+0]), SRZ * (b_ih[j+1] + b_hh[j+1]));
            v.y = pk2(SRZ * (b_ih[j+2] + b_hh[j+2]), SRZ * (b_ih[j+3] + b_hh[j+3]));
        } else {
            v.x = pk2(SN * b_hh[j+0], SN * b_hh[j+1]);
            v.y = pk2(SN * b_hh[j+2], SN * b_hh[j+3]);
        }
        sh_bias[tidb] = v;
        if (cat == 2) {
            ulonglong2 g;
            g.x = pk2(SN * b_ih[j+0], SN * b_ih[j+1]);
            g.y = pk2(SN * b_ih[j+2], SN * b_ih[j+3]);
            sh_gbias[qq] = g;
        }
    }
    if (tidb < 16) {
        sh_wsum[tidb] = w_sum[tidb];
        sh_wcar[tidb] = w_carry[tidb];
        if (tidb == 0) { sh_bs = b_sum[0]; sh_bc = b_carry[0]; }
    }
    __syncthreads();

    const int lane = tidb & 31;
    const int q    = lane & 3;
    const int g    = lane >> 2;
    const int wid  = tidb >> 5;

    ulonglong2* rb = sh_rb + wid * (RPW * RBS);

    const float ws0 = sh_wsum[4*q+0], ws1 = sh_wsum[4*q+1];
    const float ws2 = sh_wsum[4*q+2], ws3 = sh_wsum[4*q+3];
    const float wc0 = sh_wcar[4*q+0], wc1 = sh_wcar[4*q+1];
    const float wc2 = sh_wcar[4*q+2], wc3 = sh_wcar[4*q+3];
    const float bs = sh_bs, bc = sh_bc;

    const int  warp_global = blockIdx.x * 4 + wid;
    const long long rowbase0 = (long long)warp_global * (RPW * LROWS);
    if (rowbase0 >= B) return;

    #pragma unroll 1
    for (int it = 0; it < LROWS; it++) {
        const long long rbase = rowbase0 + it * RPW;

        // zero the h buffer (h0 = 0); each lane zeroes its own 32B per row
        const ulonglong2 z2 = make_ulonglong2(0, 0);
        #pragma unroll
        for (int i = 0; i < 3; i++) {
            ulonglong2* slot = rb + (i * 8 + g) * RBS;
            slot[2*q]   = z2;
            slot[2*q+1] = z2;
        }
        __syncwarp();

        ull hL[3] = {0,0,0}, hH[3] = {0,0,0};   // packed (h0,h1),(h2,h3)

        #pragma unroll 1
        for (int t = 0; t < TT; t++) {
            // init accumulators from x (constants reloaded from smem each t)
            const ulonglong2 wxr0 = sh_wx[q],      wxz0 = sh_wx[4+q],  wxn0 = sh_wx[8+q];
            const ulonglong2 wxr1 = sh_wx[12+q],   wxz1 = sh_wx[16+q], wxn1 = sh_wx[20+q];
            const ulonglong2 br = sh_bias[q], bz = sh_bias[4+q], bn = sh_bias[8+q];
            const ulonglong2 gb = sh_gbias[q];

            ull aR[3][2], aZ[3][2], aN[3][2], gN[3][2];
            #pragma unroll
            for (int i = 0; i < 3; i++) {
                const long long row = rbase + i * 8 + g;
                const long long rs  = (row < B) ? row : 0;
                const float2 xv = *reinterpret_cast<const float2*>(x + rs * (TT*II) + t*II);
                const ull xd0 = pk2(xv.x, xv.x);
                const ull xd1 = pk2(xv.y, xv.y);
                aR[i][0] = ffma2(wxr1.x, xd1, ffma2(wxr0.x, xd0, br.x));
                aR[i][1] = ffma2(wxr1.y, xd1, ffma2(wxr0.y, xd0, br.y));
                aZ[i][0] = ffma2(wxz1.x, xd1, ffma2(wxz0.x, xd0, bz.x));
                aZ[i][1] = ffma2(wxz1.y, xd1, ffma2(wxz0.y, xd0, bz.y));
                aN[i][0] = bn.x;
                aN[i][1] = bn.y;
                gN[i][0] = ffma2(wxn1.x, xd1, ffma2(wxn0.x, xd0, gb.x));
                gN[i][1] = ffma2(wxn1.y, xd1, ffma2(wxn0.y, xd0, gb.y));
            }

            // matvec: 2 k per iteration; h read from smem pre-duplicated.
            #pragma unroll
            for (int ks = 0; ks < 8; ks++) {
                const int k0 = 2 * ks, k1 = 2 * ks + 1;
                const ulonglong2 wrA = sh_whh[k0*12 + q];
                const ulonglong2 wzA = sh_whh[k0*12 + 4 + q];
                const ulonglong2 wnA = sh_whh[k0*12 + 8 + q];
                const ulonglong2 wrB = sh_whh[k1*12 + q];
                const ulonglong2 wzB = sh_whh[k1*12 + 4 + q];
                const ulonglong2 wnB = sh_whh[k1*12 + 8 + q];
                #pragma unroll
                for (int i = 0; i < 3; i++) {
                    const ulonglong2 hh = rb[(i * 8 + g) * RBS + ks]; // (dup h_k0, dup h_k1)
                    aR[i][0] = ffma2(wrB.x, hh.y, ffma2(wrA.x, hh.x, aR[i][0]));
                    aR[i][1] = ffma2(wrB.y, hh.y, ffma2(wrA.y, hh.x, aR[i][1]));
                    aZ[i][0] = ffma2(wzB.x, hh.y, ffma2(wzA.x, hh.x, aZ[i][0]));
                    aZ[i][1] = ffma2(wzB.y, hh.y, ffma2(wzA.y, hh.x, aZ[i][1]));
                    aN[i][0] = ffma2(wnB.x, hh.y, ffma2(wnA.x, hh.x, aN[i][0]));
                    aN[i][1] = ffma2(wnB.y, hh.y, ffma2(wnA.y, hh.x, aN[i][1]));
                }
            }
            __syncwarp();   // all reads of h_{t-1} done before overwrite

            // epilogue + heads per row
            #pragma unroll
            for (int i = 0; i < 3; i++) {
                const long long row = rbase + i * 8 + g;
                float hp0, hp1, hp2, hp3;
                upk2(hp0, hp1, hL[i]);
                upk2(hp2, hp3, hH[i]);
                float ar0, ar1, ar2, ar3, az0, az1, az2, az3;
                float an0, an1, an2, an3, gi0, gi1, gi2, gi3;
                upk2(ar0, ar1, aR[i][0]);  upk2(ar2, ar3, aR[i][1]);
                upk2(az0, az1, aZ[i][0]);  upk2(az2, az3, aZ[i][1]);
                upk2(an0, an1, aN[i][0]);  upk2(an2, an3, aN[i][1]);
                upk2(gi0, gi1, gN[i][0]);  upk2(gi2, gi3, gN[i][1]);
                const float r0 = fmaf(tanhapx(ar0), 0.5f, 0.5f);
                const float r1 = fmaf(tanhapx(ar1), 0.5f, 0.5f);
                const float r2 = fmaf(tanhapx(ar2), 0.5f, 0.5f);
                const float r3 = fmaf(tanhapx(ar3), 0.5f, 0.5f);
                const float z0 = fmaf(tanhapx(az0), 0.5f, 0.5f);
                const float z1 = fmaf(tanhapx(az1), 0.5f, 0.5f);
                const float z2 = fmaf(tanhapx(az2), 0.5f, 0.5f);
                const float z3 = fmaf(tanhapx(az3), 0.5f, 0.5f);
                const float n0 = ftanh_prescaled(fmaf(r0, an0, gi0));
                const float n1 = ftanh_prescaled(fmaf(r1, an1, gi1));
                const float n2 = ftanh_prescaled(fmaf(r2, an2, gi2));
                const float n3 = ftanh_prescaled(fmaf(r3, an3, gi3));
                const float h0 = fmaf(z0, hp0 - n0, n0);   // (1-z)*n + z*h
                const float h1 = fmaf(z1, hp1 - n1, n1);
                const float h2 = fmaf(z2, hp2 - n2, n2);
                const float h3 = fmaf(z3, hp3 - n3, n3);
                hL[i] = pk2(h0, h1);
                hH[i] = pk2(h2, h3);

                // write duplicated h back for next step's matvec
                ulonglong2* slot = rb + (i * 8 + g) * RBS;
                slot[2*q]   = make_ulonglong2(pk2(h0, h0), pk2(h1, h1));
                slot[2*q+1] = make_ulonglong2(pk2(h2, h2), pk2(h3, h3));

                float sp = fmaf(h3, ws3, fmaf(h2, ws2, fmaf(h1, ws1, h0 * ws0)));
                sp += __shfl_xor_sync(0xffffffffu, sp, 1);
                sp += __shfl_xor_sync(0xffffffffu, sp, 2);

                if (row < B) {
                    if (hid)
                        *reinterpret_cast<float4*>(hid + row * (TT*HH) + t*HH + 4*q) =
                            make_float4(h0, h1, h2, h3);
                    if (q == 0) {
                        if (sumo) sumo[row * TT + t] = bs + sp;
                    } else if (q == 1) {
                        if (olog) olog[row * (TT+1) + t] = bs + sp;
                    }
                }
            }
            __syncwarp();   // h_t visible to whole warp before next matvec
        }

        // carry head
        #pragma unroll
        for (int i = 0; i < 3; i++) {
            const long long row = rbase + i * 8 + g;
            float h0, h1, h2, h3;
            upk2(h0, h1, hL[i]);
            upk2(h2, h3, hH[i]);
            float cp = fmaf(h3, wc3, fmaf(h2, wc2, fmaf(h1, wc1, h0 * wc0)));
            cp += __shfl_xor_sync(0xffffffffu, cp, 1);
            cp += __shfl_xor_sync(0xffffffffu, cp, 2);
            if (row < B) {
                if (q == 2) {
                    if (carryo) carryo[row] = bc + cp;
                } else if (q == 3) {
                    if (olog) olog[row * (TT+1) + TT] = bc + cp;
                }
            }
        }
    }
}

extern "C" void kernel_launch(void* const* d_in, const int* in_sizes, int n_in,
                              void* d_out, int out_size) {
    const float* x       = (const float*)d_in[0];
    const float* w_ih    = (const float*)d_in[1];
    const float* w_hh    = (const float*)d_in[2];
    const float* b_ih    = (const float*)d_in[3];
    const float* b_hh    = (const float*)d_in[4];
    const float* w_sum   = (const float*)d_in[5];
    const float* b_sum   = (const float*)d_in[6];
    const float* w_carry = (const float*)d_in[7];
    const float* b_carry = (const float*)d_in[8];

    long long B = (long long)in_sizes[0] / (TT * II);
    float* out = (float*)d_out;
    long long os = (long long)out_size;

    // Output layout: concatenation of flattened (hidden_table, sum_logits,
    // carry_logit, output_logits) = 74 floats per row; fall back otherwise.
    float *hid = nullptr, *sum = nullptr, *car = nullptr, *olog = nullptr;
    if (os >= B * 74) {
        hid = out; sum = out + B * 64; car = out + B * 68; olog = out + B * 69;
    } else if (os >= B * 64) {
        hid = out;
    } else if (os >= B * 5) {
        olog = out;
    } else if (os >= B * 4) {
        sum = out;
    } else {
        car = out;
    }

    const int threads = 128;                        // 4 warps per CTA
    const long long rows_per_warp = RPW * LROWS;    // 48
    long long warps = (B + rows_per_warp - 1) / rows_per_warp;
    long long ctas  = (warps + 3) / 4;
    gru_adder_kernel<<<(int)ctas, threads>>>(x, w_ih, w_hh, b_ih, b_hh,
                                             w_sum, b_sum, w_carry, b_carry,
                                             hid, sum, car, olog, B);
}

// round 15
// speedup vs baseline: 1.5406x; 1.2437x over previous
#include <cuda_runtime.h>

// GRUAdder: B = 1048576, T=4, I=2, H=16.
// L=4 lanes per row (lane q owns h[4q..4q+3], gates {4q..4q+3} of r/z/n),
// D=3 rows per thread. Gate-pair packed f32x2 accumulators.
// h exchanged through a per-warp SMEM buffer, NON-duplicated (64B/row),
// with XOR-swizzled 16B columns (col = x ^ (g>>1), stride 64B) making both
// the per-lane writes and the per-quad reads bank-conflict-free.
// t=0 is specialized: h_prev = 0 so the entire matvec is skipped.
// Sigmoid via tanh.approx (0.5 pre-folded into staged weights); n-gate tanh
// via ex2/rcp with -2*log2(e) pre-folded.

#define TT 4
#define II 2
#define HH 16
#define LROWS 2         // iterations; rows per warp = 24 * LROWS = 48
#define RPW 24          // rows in flight per warp (8 groups x 3)

#define SRZ 0.5f
#define SN  (-2.8853900817779268f)   // -2*log2(e)

typedef unsigned long long ull;

__device__ __forceinline__ ull ffma2(ull a, ull b, ull c) {
    ull d;
    asm("fma.rn.f32x2 %0, %1, %2, %3;" : "=l"(d) : "l"(a), "l"(b), "l"(c));
    return d;
}
__device__ __forceinline__ ull pk2(float lo, float hi) {
    ull r;
    asm("mov.b64 %0, {%1, %2};" : "=l"(r) : "f"(lo), "f"(hi));
    return r;
}
__device__ __forceinline__ void upk2(float& lo, float& hi, ull v) {
    asm("mov.b64 {%0, %1}, %2;" : "=f"(lo), "=f"(hi) : "l"(v));
}
__device__ __forceinline__ float tanhapx(float x) {
    float r;
    asm("tanh.approx.f32 %0, %1;" : "=f"(r) : "f"(x));
    return r;
}
// argument already scaled by -2*log2(e): returns tanh(y) where a = SN*y
__device__ __forceinline__ float ftanh_prescaled(float a) {
    float e, r;
    asm("ex2.approx.f32 %0, %1;" : "=f"(e) : "f"(a));
    asm("rcp.approx.f32 %0, %1;" : "=f"(r) : "f"(1.0f + e));
    return fmaf(2.0f, r, -1.0f);
}

__global__ void __launch_bounds__(128) gru_adder_kernel(
    const float* __restrict__ x,        // [B, 4, 2]
    const float* __restrict__ w_ih,     // [48, 2]
    const float* __restrict__ w_hh,     // [48, 16]
    const float* __restrict__ b_ih,     // [48]
    const float* __restrict__ b_hh,     // [48]
    const float* __restrict__ w_sum,    // [1, 16]
    const float* __restrict__ b_sum,    // [1]
    const float* __restrict__ w_carry,  // [1, 16]
    const float* __restrict__ b_carry,  // [1]
    float* __restrict__ hid,            // [B, 4, 16]
    float* __restrict__ sumo,           // [B, 4]
    float* __restrict__ carryo,         // [B]
    float* __restrict__ olog,           // [B, 5]
    long long B)
{
    // Weights, gate-pair packed: sh_whh[k*12 + cat*4 + q] =
    //   { pk2(sc*w[j][k], sc*w[j+1][k]), pk2(sc*w[j+2][k], sc*w[j+3][k]) }
    //   with j = cat*16 + 4q; sc = 0.5 (r,z), SN (n).
    __shared__ __align__(16) ulonglong2 sh_whh[16 * 12];
    __shared__ __align__(16) ulonglong2 sh_wx[2 * 12];   // per input col
    __shared__ __align__(16) ulonglong2 sh_bias[12];     // pair bias seeds
    __shared__ __align__(16) ulonglong2 sh_gbias[4];     // n input-bias pairs
    __shared__ __align__(16) float sh_wsum[16], sh_wcar[16];
    __shared__ float sh_bs, sh_bc;
    // Per-warp h buffer: RPW slots x 64B (4 x 16B swizzled columns).
    __shared__ __align__(16) ulonglong2 sh_rb[4 * RPW * 4];

    const int tidb = threadIdx.x;
    for (int idx = tidb; idx < 192; idx += 128) {
        int k = idx / 12, rem = idx % 12, cat = rem / 4, qq = rem % 4;
        int j = cat * 16 + 4 * qq;
        float sc = (cat < 2) ? SRZ : SN;
        ulonglong2 v;
        v.x = pk2(sc * w_hh[(j + 0) * HH + k], sc * w_hh[(j + 1) * HH + k]);
        v.y = pk2(sc * w_hh[(j + 2) * HH + k], sc * w_hh[(j + 3) * HH + k]);
        sh_whh[idx] = v;
    }
    if (tidb < 24) {
        int col = tidb / 12, rem = tidb % 12, cat = rem / 4, qq = rem % 4;
        int j = cat * 16 + 4 * qq;
        float sc = (cat < 2) ? SRZ : SN;
        ulonglong2 v;
        v.x = pk2(sc * w_ih[(j + 0) * II + col], sc * w_ih[(j + 1) * II + col]);
        v.y = pk2(sc * w_ih[(j + 2) * II + col], sc * w_ih[(j + 3) * II + col]);
        sh_wx[tidb] = v;
    }
    if (tidb < 12) {
        int cat = tidb / 4, qq = tidb % 4;
        int j = cat * 16 + 4 * qq;
        ulonglong2 v;
        if (cat < 2) {
            v.x = pk2(SRZ * (b_ih[j+0] + b_hh[j+0]), SRZ * (b_ih[j+1] + b_hh[j+1]));
            v.y = pk2(SRZ * (b_ih[j+2] + b_hh[j+2]), SRZ * (b_ih[j+3] + b_hh[j+3]));
        } else {
            v.x = pk2(SN * b_hh[j+0], SN * b_hh[j+1]);
            v.y = pk2(SN * b_hh[j+2], SN * b_hh[j+3]);
        }
        sh_bias[tidb] = v;
        if (cat == 2) {
            ulonglong2 gg;
            gg.x = pk2(SN * b_ih[j+0], SN * b_ih[j+1]);
            gg.y = pk2(SN * b_ih[j+2], SN * b_ih[j+3]);
            sh_gbias[qq] = gg;
        }
    }
    if (tidb < 16) {
        sh_wsum[tidb] = w_sum[tidb];
        sh_wcar[tidb] = w_carry[tidb];
        if (tidb == 0) { sh_bs = b_sum[0]; sh_bc = b_carry[0]; }
    }
    __syncthreads();

    const int lane = tidb & 31;
    const int q    = lane & 3;
    const int g    = lane >> 2;
    const int gs   = g >> 1;          // swizzle key (0..3)
    const int wid  = tidb >> 5;

    ulonglong2* rbu2 = sh_rb + wid * (RPW * 4);

    const float ws0 = sh_wsum[4*q+0], ws1 = sh_wsum[4*q+1];
    const float ws2 = sh_wsum[4*q+2], ws3 = sh_wsum[4*q+3];
    const float wc0 = sh_wcar[4*q+0], wc1 = sh_wcar[4*q+1];
    const float wc2 = sh_wcar[4*q+2], wc3 = sh_wcar[4*q+3];
    const float bs = sh_bs, bc = sh_bc;

    const int  warp_global = blockIdx.x * 4 + wid;
    const long long rowbase0 = (long long)warp_global * (RPW * LROWS);
    if (rowbase0 >= B) return;

    #pragma unroll 1
    for (int it = 0; it < LROWS; it++) {
        const long long rbase = rowbase0 + it * RPW;

        ull hL[3] = {0,0,0}, hH[3] = {0,0,0};   // packed (h0,h1),(h2,h3)

        #pragma unroll 1
        for (int t = 0; t < TT; t++) {
            // init accumulators from x (constants reloaded from smem each t)
            const ulonglong2 wxr0 = sh_wx[q],      wxz0 = sh_wx[4+q],  wxn0 = sh_wx[8+q];
            const ulonglong2 wxr1 = sh_wx[12+q],   wxz1 = sh_wx[16+q], wxn1 = sh_wx[20+q];
            const ulonglong2 br = sh_bias[q], bz = sh_bias[4+q], bn = sh_bias[8+q];
            const ulonglong2 gb = sh_gbias[q];

            ull aR[3][2], aZ[3][2], aN[3][2], gN[3][2];
            #pragma unroll
            for (int i = 0; i < 3; i++) {
                const long long row = rbase + i * 8 + g;
                const long long rs  = (row < B) ? row : 0;
                const float2 xv = *reinterpret_cast<const float2*>(x + rs * (TT*II) + t*II);
                const ull xd0 = pk2(xv.x, xv.x);
                const ull xd1 = pk2(xv.y, xv.y);
                aR[i][0] = ffma2(wxr1.x, xd1, ffma2(wxr0.x, xd0, br.x));
                aR[i][1] = ffma2(wxr1.y, xd1, ffma2(wxr0.y, xd0, br.y));
                aZ[i][0] = ffma2(wxz1.x, xd1, ffma2(wxz0.x, xd0, bz.x));
                aZ[i][1] = ffma2(wxz1.y, xd1, ffma2(wxz0.y, xd0, bz.y));
                aN[i][0] = bn.x;
                aN[i][1] = bn.y;
                gN[i][0] = ffma2(wxn1.x, xd1, ffma2(wxn0.x, xd0, gb.x));
                gN[i][1] = ffma2(wxn1.y, xd1, ffma2(wxn0.y, xd0, gb.y));
            }

            // matvec (skipped at t=0: h_prev == 0 contributes nothing)
            if (t) {
                #pragma unroll
                for (int c = 0; c < 4; c++) {        // k-quads: k = 4c..4c+3
                    float f[3][4];
                    #pragma unroll
                    for (int i = 0; i < 3; i++) {
                        const ulonglong2 hh = rbu2[((i*8+g) << 2) + (c ^ gs)];
                        upk2(f[i][0], f[i][1], hh.x);
                        upk2(f[i][2], f[i][3], hh.y);
                    }
                    #pragma unroll
                    for (int kk = 0; kk < 4; kk++) {
                        const int k = 4*c + kk;
                        const ulonglong2 wr = sh_whh[k*12 + q];
                        const ulonglong2 wz = sh_whh[k*12 + 4 + q];
                        const ulonglong2 wn = sh_whh[k*12 + 8 + q];
                        #pragma unroll
                        for (int i = 0; i < 3; i++) {
                            const ull hd = pk2(f[i][kk], f[i][kk]);
                            aR[i][0] = ffma2(wr.x, hd, aR[i][0]);
                            aR[i][1] = ffma2(wr.y, hd, aR[i][1]);
                            aZ[i][0] = ffma2(wz.x, hd, aZ[i][0]);
                            aZ[i][1] = ffma2(wz.y, hd, aZ[i][1]);
                            aN[i][0] = ffma2(wn.x, hd, aN[i][0]);
                            aN[i][1] = ffma2(wn.y, hd, aN[i][1]);
                        }
                    }
                }
            }
            __syncwarp();   // all reads of h_{t-1} done before overwrite

            // epilogue + heads per row
            #pragma unroll
            for (int i = 0; i < 3; i++) {
                const long long row = rbase + i * 8 + g;
                float hp0, hp1, hp2, hp3;
                upk2(hp0, hp1, hL[i]);
                upk2(hp2, hp3, hH[i]);
                float ar0, ar1, ar2, ar3, az0, az1, az2, az3;
                float an0, an1, an2, an3, gi0, gi1, gi2, gi3;
                upk2(ar0, ar1, aR[i][0]);  upk2(ar2, ar3, aR[i][1]);
                upk2(az0, az1, aZ[i][0]);  upk2(az2, az3, aZ[i][1]);
                upk2(an0, an1, aN[i][0]);  upk2(an2, an3, aN[i][1]);
                upk2(gi0, gi1, gN[i][0]);  upk2(gi2, gi3, gN[i][1]);
                const float r0 = fmaf(tanhapx(ar0), 0.5f, 0.5f);
                const float r1 = fmaf(tanhapx(ar1), 0.5f, 0.5f);
                const float r2 = fmaf(tanhapx(ar2), 0.5f, 0.5f);
                const float r3 = fmaf(tanhapx(ar3), 0.5f, 0.5f);
                const float z0 = fmaf(tanhapx(az0), 0.5f, 0.5f);
                const float z1 = fmaf(tanhapx(az1), 0.5f, 0.5f);
                const float z2 = fmaf(tanhapx(az2), 0.5f, 0.5f);
                const float z3 = fmaf(tanhapx(az3), 0.5f, 0.5f);
                const float n0 = ftanh_prescaled(fmaf(r0, an0, gi0));
                const float n1 = ftanh_prescaled(fmaf(r1, an1, gi1));
                const float n2 = ftanh_prescaled(fmaf(r2, an2, gi2));
                const float n3 = ftanh_prescaled(fmaf(r3, an3, gi3));
                const float h0 = fmaf(z0, hp0 - n0, n0);   // (1-z)*n + z*h
                const float h1 = fmaf(z1, hp1 - n1, n1);
                const float h2 = fmaf(z2, hp2 - n2, n2);
                const float h3 = fmaf(z3, hp3 - n3, n3);
                hL[i] = pk2(h0, h1);
                hH[i] = pk2(h2, h3);

                // write packed h back (non-dup, swizzled column) for next step
                rbu2[((i*8+g) << 2) + (q ^ gs)] = make_ulonglong2(hL[i], hH[i]);

                float sp = fmaf(h3, ws3, fmaf(h2, ws2, fmaf(h1, ws1, h0 * ws0)));
                sp += __shfl_xor_sync(0xffffffffu, sp, 1);
                sp += __shfl_xor_sync(0xffffffffu, sp, 2);

                if (row < B) {
                    if (hid)
                        *reinterpret_cast<float4*>(hid + row * (TT*HH) + t*HH + 4*q) =
                            make_float4(h0, h1, h2, h3);
                    if (q == 0) {
                        if (sumo) sumo[row * TT + t] = bs + sp;
                    } else if (q == 1) {
                        if (olog) olog[row * (TT+1) + t] = bs + sp;
                    }
                }
            }
            __syncwarp();   // h_t visible to whole warp before next matvec
        }

        // carry head
        #pragma unroll
        for (int i = 0; i < 3; i++) {
            const long long row = rbase + i * 8 + g;
            float h0, h1, h2, h3;
            upk2(h0, h1, hL[i]);
            upk2(h2, h3, hH[i]);
            float cp = fmaf(h3, wc3, fmaf(h2, wc2, fmaf(h1, wc1, h0 * wc0)));
            cp += __shfl_xor_sync(0xffffffffu, cp, 1);
            cp += __shfl_xor_sync(0xffffffffu, cp, 2);
            if (row < B) {
                if (q == 2) {
                    if (carryo) carryo[row] = bc + cp;
                } else if (q == 3) {
                    if (olog) olog[row * (TT+1) + TT] = bc + cp;
                }
            }
        }
    }
}

extern "C" void kernel_launch(void* const* d_in, const int* in_sizes, int n_in,
                              void* d_out, int out_size) {
    const float* x       = (const float*)d_in[0];
    const float* w_ih    = (const float*)d_in[1];
    const float* w_hh    = (const float*)d_in[2];
    const float* b_ih    = (const float*)d_in[3];
    const float* b_hh    = (const float*)d_in[4];
    const float* w_sum   = (const float*)d_in[5];
    const float* b_sum   = (const float*)d_in[6];
    const float* w_carry = (const float*)d_in[7];
    const float* b_carry = (const float*)d_in[8];

    long long B = (long long)in_sizes[0] / (TT * II);
    float* out = (float*)d_out;
    long long os = (long long)out_size;

    // Output layout: concatenation of flattened (hidden_table, sum_logits,
    // carry_logit, output_logits) = 74 floats per row; fall back otherwise.
    float *hid = nullptr, *sum = nullptr, *car = nullptr, *olog = nullptr;
    if (os >= B * 74) {
        hid = out; sum = out + B * 64; car = out + B * 68; olog = out + B * 69;
    } else if (os >= B * 64) {
        hid = out;
    } else if (os >= B * 5) {
        olog = out;
    } else if (os >= B * 4) {
        sum = out;
    } else {
        car = out;
    }

    const int threads = 128;                        // 4 warps per CTA
    const long long rows_per_warp = RPW * LROWS;    // 48
    long long warps = (B + rows_per_warp - 1) / rows_per_warp;
    long long ctas  = (warps + 3) / 4;
    gru_adder_kernel<<<(int)ctas, threads>>>(x, w_ih, w_hh, b_ih, b_hh,
                                             w_sum, b_sum, w_carry, b_carry,
                                             hid, sum, car, olog, B);
}